// round 10
// baseline (speedup 1.0000x reference)
#include <cuda_runtime.h>
#include <cuda_bf16.h>
#include <cuda_fp16.h>
#include <cstdint>

// Problem constants
#define B_   2
#define N_   4096
#define C_   512
#define H_   8
#define D_   64
#define INNER_ (H_ * D_)          // 512
#define QKVCOLS_ (INNER_ * 3)     // 1536
#define M_ (B_ * N_)              // 8192
#define R_TOTAL (B_ * H_ * N_)    // 65536 rows of 64

// Scratch (device globals; no cudaMalloc allowed)
__device__ __half g_qh[R_TOTAL * D_];
__device__ __half g_kh[R_TOTAL * D_];
__device__ __half g_vh[R_TOTAL * D_];
__device__ __half g_xh[M_ * C_], g_xl[M_ * C_];
__device__ __half g_wq[C_ * QKVCOLS_];
__device__ __half g_wo[INNER_ * C_];
__device__ __half g_ohh[B_ * N_ * INNER_], g_ohl[B_ * N_ * INNER_];

#define SCALE_LOG2E (0.125f * 1.4426950408889634f)
#define ONES_H2 0x3C003C00u

// ---------------------------------------------------------------------------
// common helpers
// ---------------------------------------------------------------------------
__device__ __forceinline__ uint32_t u32h2(__half2 v)
{
    return reinterpret_cast<uint32_t&>(v);
}
__device__ __forceinline__ float ex2(float x)
{
    float y;
    asm("ex2.approx.ftz.f32 %0, %1;" : "=f"(y) : "f"(x));
    return y;
}
__device__ __forceinline__ uint32_t hex2(__half2 v)
{
    uint32_t y;
    asm("ex2.approx.f16x2 %0, %1;" : "=r"(y) : "r"(u32h2(v)));
    return y;
}
__device__ __forceinline__ uint32_t swz(uint32_t row, uint32_t colb)
{
    uint32_t b = (row << 7) + colb;     // 128B rows
    return b ^ ((b >> 3) & 0x70);
}
__device__ __forceinline__ uint32_t swzA(uint32_t row, uint32_t colb)
{
    uint32_t b = (row << 6) + colb;     // 64B rows
    return b ^ ((b >> 3) & 0x30);
}
__device__ __forceinline__ void cp16(uint32_t dst, const void* src)
{
    asm volatile("cp.async.cg.shared.global [%0], [%1], 16;"
                 :: "r"(dst), "l"(src));
}
__device__ __forceinline__ void cp_commit()
{
    asm volatile("cp.async.commit_group;");
}
__device__ __forceinline__ void cp_wait0()
{
    asm volatile("cp.async.wait_group 0;");
}
__device__ __forceinline__ void cp_wait1()
{
    asm volatile("cp.async.wait_group 1;");
}
__device__ __forceinline__ void ldsm4(uint32_t a[4], uint32_t addr)
{
    asm volatile("ldmatrix.sync.aligned.m8n8.x4.shared.b16 {%0,%1,%2,%3}, [%4];"
                 : "=r"(a[0]), "=r"(a[1]), "=r"(a[2]), "=r"(a[3]) : "r"(addr));
}
__device__ __forceinline__ void ldsm4t(uint32_t a[4], uint32_t addr)
{
    asm volatile("ldmatrix.sync.aligned.m8n8.x4.trans.shared.b16 {%0,%1,%2,%3}, [%4];"
                 : "=r"(a[0]), "=r"(a[1]), "=r"(a[2]), "=r"(a[3]) : "r"(addr));
}
__device__ __forceinline__ void mma16816h(float c[4], const uint32_t a[4],
                                          uint32_t b0, uint32_t b1)
{
    asm volatile(
        "mma.sync.aligned.m16n8k16.row.col.f32.f16.f16.f32 "
        "{%0,%1,%2,%3}, {%4,%5,%6,%7}, {%8,%9}, {%0,%1,%2,%3};"
        : "+f"(c[0]), "+f"(c[1]), "+f"(c[2]), "+f"(c[3])
        : "r"(a[0]), "r"(a[1]), "r"(a[2]), "r"(a[3]), "r"(b0), "r"(b1));
}

// ---------------------------------------------------------------------------
// K0: merged conversion — x -> hi/lo split; w_qkv, w_out -> fp16 single.
// ---------------------------------------------------------------------------
#define N4X  (M_ * C_ / 4)
#define N4WQ (C_ * QKVCOLS_ / 4)
#define N4WO (INNER_ * C_ / 4)
#define N4ALL (N4X + N4WQ + N4WO)

__global__ __launch_bounds__(256) void conv_all_kernel(
    const float4* __restrict__ x, const float4* __restrict__ wq,
    const float4* __restrict__ wo)
{
    int i = blockIdx.x * 256 + threadIdx.x;
    if (i < N4X) {
        float4 f = x[i];
        __half2 h0 = __floats2half2_rn(f.x, f.y);
        __half2 h1 = __floats2half2_rn(f.z, f.w);
        float2 a = __half22float2(h0), b = __half22float2(h1);
        __half2 l0 = __floats2half2_rn(f.x - a.x, f.y - a.y);
        __half2 l1 = __floats2half2_rn(f.z - b.x, f.w - b.y);
        ((uint2*)g_xh)[i] = make_uint2(u32h2(h0), u32h2(h1));
        ((uint2*)g_xl)[i] = make_uint2(u32h2(l0), u32h2(l1));
    } else if (i < N4X + N4WQ) {
        int j = i - N4X;
        float4 f = wq[j];
        ((uint2*)g_wq)[j] = make_uint2(u32h2(__floats2half2_rn(f.x, f.y)),
                                       u32h2(__floats2half2_rn(f.z, f.w)));
    } else if (i < N4ALL) {
        int j = i - N4X - N4WQ;
        float4 f = wo[j];
        ((uint2*)g_wo)[j] = make_uint2(u32h2(__floats2half2_rn(f.x, f.y)),
                                       u32h2(__floats2half2_rn(f.z, f.w)));
    }
}

// ---------------------------------------------------------------------------
// K1: QKV GEMM. BM=128, BN=128, BK=32, 3-stage cp.async, fp16 2-term.
// Fused epilogue: RoPE + scale(q) + fp16 convert + scatter.
// ---------------------------------------------------------------------------
#define QSA_H 0
#define QSA_L 8192
#define QSB   16384       // + half*4096
#define QSTAGE 24576
#define QSMEM (3 * QSTAGE)   // 73728
#define GNKT (C_ / 32)    // 16

__device__ __forceinline__ void qkv_stage(
    uint32_t sb, uint32_t stg, int m0, int n0, int k0, int tid)
{
    #pragma unroll
    for (int i = 0; i < 6; i++) {
        int c = tid + i * 256;               // 0..1535
        if (c < 512) {
            int row = c >> 2, col16 = c & 3;
            cp16(sb + stg + QSA_H + swzA(row, col16 * 16),
                 g_xh + (size_t)(m0 + row) * C_ + k0 + col16 * 8);
        } else if (c < 1024) {
            int cc = c - 512;
            int row = cc >> 2, col16 = cc & 3;
            cp16(sb + stg + QSA_L + swzA(row, col16 * 16),
                 g_xl + (size_t)(m0 + row) * C_ + k0 + col16 * 8);
        } else {
            int cc = c - 1024;               // 0..511
            int row = cc >> 4;               // 0..31
            int col16 = cc & 15;
            int half = col16 >> 3;
            cp16(sb + stg + QSB + half * 4096 + swz(row, (col16 & 7) * 16),
                 g_wq + (size_t)(k0 + row) * QKVCOLS_ + n0 + col16 * 8);
        }
    }
}

__global__ __launch_bounds__(256) void gemm_qkv_mma(const float* __restrict__ pos)
{
    extern __shared__ char smemq[];
    const uint32_t sb = (uint32_t)__cvta_generic_to_shared(smemq);
    const int tid = threadIdx.x;
    const int wid = tid >> 5, lane = tid & 31;
    const int wm = wid >> 1, wn = wid & 1;
    const int m0 = blockIdx.y * 128;
    const int n0 = blockIdx.x * 128;

    float c[2][8][4] = {};

    qkv_stage(sb, 0,          m0, n0, 0,  tid);
    cp_commit();
    qkv_stage(sb, QSTAGE,     m0, n0, 32, tid);
    cp_commit();

    const int rA = lane & 15;
    const int cadd = (lane & 16) ? 16 : 0;

    for (int kt = 0; kt < GNKT; kt++) {
        if (kt < GNKT - 1) cp_wait1(); else cp_wait0();
        __syncthreads();
        if (kt + 2 < GNKT) {
            qkv_stage(sb, ((kt + 2) % 3) * QSTAGE, m0, n0, (kt + 2) * 32, tid);
            cp_commit();
        }
        const uint32_t stg = (kt % 3) * QSTAGE;
        #pragma unroll
        for (int t = 0; t < 2; t++) {
            uint32_t AH[2][4], AL[2][4], BW[4][4];
            #pragma unroll
            for (int mi = 0; mi < 2; mi++) {
                uint32_t off = swzA(wm * 32 + mi * 16 + rA, t * 32 + cadd);
                ldsm4(AH[mi], sb + stg + QSA_H + off);
                ldsm4(AL[mi], sb + stg + QSA_L + off);
            }
            #pragma unroll
            for (int j2 = 0; j2 < 4; j2++) {
                uint32_t off = swz(t * 16 + rA, j2 * 32 + cadd);
                ldsm4t(BW[j2], sb + stg + QSB + wn * 4096 + off);
            }
            #pragma unroll
            for (int mi = 0; mi < 2; mi++) {
                #pragma unroll
                for (int j2 = 0; j2 < 4; j2++) {
                    mma16816h(c[mi][2 * j2],     AH[mi], BW[j2][0], BW[j2][1]);
                    mma16816h(c[mi][2 * j2 + 1], AH[mi], BW[j2][2], BW[j2][3]);
                    mma16816h(c[mi][2 * j2],     AL[mi], BW[j2][0], BW[j2][1]);
                    mma16816h(c[mi][2 * j2 + 1], AL[mi], BW[j2][2], BW[j2][3]);
                }
            }
        }
    }

    // fused epilogue: RoPE (q,k) + scale(q) + fp16 convert + scatter
    const int part = n0 >> 9;                          // 0=q, 1=k, 2=v
    const int h = ((n0 + wn * 64) & 511) >> 6;
    __half* dst = (part == 0) ? g_qh : (part == 1) ? g_kh : g_vh;

    #pragma unroll
    for (int mi = 0; mi < 2; mi++) {
        #pragma unroll
        for (int r8 = 0; r8 < 2; r8++) {
            const int mrow = m0 + wm * 32 + mi * 16 + r8 * 8 + (lane >> 2);
            const int b = mrow >> 12;
            const int n = mrow & (N_ - 1);
            const size_t base = ((size_t)(b * H_ + h) * N_ + n) * D_;
            #pragma unroll
            for (int nj = 0; nj < 8; nj++) {
                const int dd = nj * 8 + (lane & 3) * 2;
                float v0 = c[mi][nj][2 * r8];
                float v1 = c[mi][nj][2 * r8 + 1];
                float r0, r1;
                if (part < 2) {
                    float s0, c0, s1, c1;
                    __sincosf(pos[n * D_ + dd],     &s0, &c0);
                    __sincosf(pos[n * D_ + dd + 1], &s1, &c1);
                    const float q0 = c[mi][nj ^ 4][2 * r8];
                    const float q1 = c[mi][nj ^ 4][2 * r8 + 1];
                    const float sign = (nj < 4) ? -1.0f : 1.0f;
                    r0 = v0 * c0 + sign * q0 * s0;
                    r1 = v1 * c1 + sign * q1 * s1;
                    if (part == 0) { r0 *= SCALE_LOG2E; r1 *= SCALE_LOG2E; }
                } else {
                    r0 = v0; r1 = v1;
                }
                *(uint32_t*)&dst[base + dd] = u32h2(__floats2half2_rn(r0, r1));
            }
        }
    }
}

// ---------------------------------------------------------------------------
// K4: output GEMM. BM=128, BN=64, BK=32, 3-stage cp.async, fp16 2-term.
// ---------------------------------------------------------------------------
#define GSA_H 0
#define GSA_L 8192
#define GSB   16384
#define GSTAGE 20480
#define GSMEM (3 * GSTAGE)   // 61440

__device__ __forceinline__ void out_stage(
    uint32_t sb, uint32_t stg, int m0, int n0, int k0, int tid)
{
    #pragma unroll
    for (int i = 0; i < 5; i++) {
        int c = tid + i * 256;               // 0..1279
        if (c < 512) {
            int row = c >> 2, col16 = c & 3;
            cp16(sb + stg + GSA_H + swzA(row, col16 * 16),
                 g_ohh + (size_t)(m0 + row) * C_ + k0 + col16 * 8);
        } else if (c < 1024) {
            int cc = c - 512;
            int row = cc >> 2, col16 = cc & 3;
            cp16(sb + stg + GSA_L + swzA(row, col16 * 16),
                 g_ohl + (size_t)(m0 + row) * C_ + k0 + col16 * 8);
        } else {
            int cc = c - 1024;
            int row = cc >> 3, col16 = cc & 7;
            cp16(sb + stg + GSB + swz(row, col16 * 16),
                 g_wo + (size_t)(k0 + row) * C_ + n0 + col16 * 8);
        }
    }
}

__global__ __launch_bounds__(256) void gemm_out_mma(
    const float* __restrict__ bias, float* __restrict__ out)
{
    extern __shared__ char smemo[];
    const uint32_t sb = (uint32_t)__cvta_generic_to_shared(smemo);
    const int tid = threadIdx.x;
    const int wid = tid >> 5, lane = tid & 31;
    const int wm = wid >> 1, wn = wid & 1;
    const int m0 = blockIdx.y * 128;
    const int n0 = blockIdx.x * 64;

    float c[2][4][4] = {};

    out_stage(sb, 0,      m0, n0, 0,  tid);
    cp_commit();
    out_stage(sb, GSTAGE, m0, n0, 32, tid);
    cp_commit();

    const int rA = lane & 15;
    const int cadd = (lane & 16) ? 16 : 0;

    for (int kt = 0; kt < GNKT; kt++) {
        if (kt < GNKT - 1) cp_wait1(); else cp_wait0();
        __syncthreads();
        if (kt + 2 < GNKT) {
            out_stage(sb, ((kt + 2) % 3) * GSTAGE, m0, n0, (kt + 2) * 32, tid);
            cp_commit();
        }
        const uint32_t stg = (kt % 3) * GSTAGE;
        #pragma unroll
        for (int t = 0; t < 2; t++) {
            uint32_t AH[2][4], AL[2][4], BW[2][4];
            #pragma unroll
            for (int mi = 0; mi < 2; mi++) {
                uint32_t off = swzA(wm * 32 + mi * 16 + rA, t * 32 + cadd);
                ldsm4(AH[mi], sb + stg + GSA_H + off);
                ldsm4(AL[mi], sb + stg + GSA_L + off);
            }
            #pragma unroll
            for (int j2 = 0; j2 < 2; j2++) {
                uint32_t off = swz(t * 16 + rA, wn * 64 + j2 * 32 + cadd);
                ldsm4t(BW[j2], sb + stg + GSB + off);
            }
            #pragma unroll
            for (int mi = 0; mi < 2; mi++) {
                #pragma unroll
                for (int j2 = 0; j2 < 2; j2++) {
                    mma16816h(c[mi][2 * j2],     AH[mi], BW[j2][0], BW[j2][1]);
                    mma16816h(c[mi][2 * j2 + 1], AH[mi], BW[j2][2], BW[j2][3]);
                    mma16816h(c[mi][2 * j2],     AL[mi], BW[j2][0], BW[j2][1]);
                    mma16816h(c[mi][2 * j2 + 1], AL[mi], BW[j2][2], BW[j2][3]);
                }
            }
        }
    }

    #pragma unroll
    for (int mi = 0; mi < 2; mi++) {
        #pragma unroll
        for (int r8 = 0; r8 < 2; r8++) {
            const int mrow = m0 + wm * 32 + mi * 16 + r8 * 8 + (lane >> 2);
            #pragma unroll
            for (int nj = 0; nj < 4; nj++) {
                const int col = n0 + wn * 32 + nj * 8 + (lane & 3) * 2;
                *(float2*)&out[(size_t)mrow * C_ + col] =
                    make_float2(c[mi][nj][2 * r8] + bias[col],
                                c[mi][nj][2 * r8 + 1] + bias[col + 1]);
            }
        }
    }
}

// ---------------------------------------------------------------------------
// K3: flash attention, fp16 mma.sync, BC=64, l via ones-MMA, f16x2 exp.
// ---------------------------------------------------------------------------
#define BR 128
#define BC 64
#define NT (N_ / BC)       // 64

#define SQ    0
#define SKV   16384        // + stage*16384 ; K at +0, V at +8192
#define SMEM_BYTES 49152

__global__ __launch_bounds__(256, 2) void flash_mma_kernel()
{
    extern __shared__ char smraw[];
    const uint32_t sb = (uint32_t)__cvta_generic_to_shared(smraw);

    const int tid = threadIdx.x;
    const int wid = tid >> 5;
    const int lane = tid & 31;
    const int bh = blockIdx.y;
    const int b = bh >> 3, h = bh & 7;
    const int q0 = blockIdx.x * BR;

    // ---- stage Q ----
    {
        const size_t qbase = ((size_t)bh * N_ + q0) * D_;
        #pragma unroll
        for (int i = 0; i < 4; i++) {
            int c = tid + i * 256;
            int row = c >> 3;
            int col16 = c & 7;
            cp16(sb + SQ + swz(row, col16 * 16),
                 g_qh + qbase + (size_t)row * D_ + col16 * 8);
        }
    }
    // ---- stage KV tile 0 ----
    {
        const size_t kvbase = (size_t)bh * N_ * D_;
        #pragma unroll
        for (int i = 0; i < 4; i++) {
            int c = tid + i * 256;
            int arr = c >> 9;
            int cc = c & 511;
            int row = cc >> 3;
            int col16 = cc & 7;
            cp16(sb + SKV + (arr ? 8192 : 0) + swz(row, col16 * 16),
                 (arr ? g_vh : g_kh) + kvbase + (size_t)row * D_ + col16 * 8);
        }
    }
    cp_commit();
    cp_wait0();
    __syncthreads();

    // ---- Q fragments (registers, whole kernel) ----
    const int m0 = wid * 16;
    uint32_t qh[4][4];
    {
        int r = m0 + (lane & 15);
        int cadd = (lane & 16) ? 16 : 0;
        #pragma unroll
        for (int t = 0; t < 4; t++)
            ldsm4(qh[t], sb + SQ + swz(r, t * 32 + cadd));
    }

    float o[8][4] = {};
    float lacc[4] = {};
    float mrow0 = -1e30f, mrow1 = -1e30f;

    const size_t kvstride = (size_t)bh * N_ * D_;

    for (int kt = 0; kt < NT; kt++) {
        const uint32_t buf = (kt & 1) ? 16384 : 0;
        const uint32_t nbuf = (kt & 1) ? 0 : 16384;

        if (kt + 1 < NT) {
            const size_t kvbase = kvstride + (size_t)(kt + 1) * BC * D_;
            #pragma unroll
            for (int i = 0; i < 4; i++) {
                int c = tid + i * 256;
                int arr = c >> 9;
                int cc = c & 511;
                int row = cc >> 3;
                int col16 = cc & 7;
                cp16(sb + SKV + nbuf + (arr ? 8192 : 0) + swz(row, col16 * 16),
                     (arr ? g_vh : g_kh) + kvbase + (size_t)row * D_ + col16 * 8);
            }
            cp_commit();
        }

        // ---- S = Q K^T (raw, fp32 accum) ----
        float s[8][4] = {};
        {
            const int rbase = lane & 15;
            const int cadd = (lane & 16) ? 16 : 0;
            #pragma unroll
            for (int p = 0; p < 4; p++) {
                #pragma unroll
                for (int t = 0; t < 4; t++) {
                    uint32_t KH[4];
                    ldsm4(KH, sb + SKV + buf + swz(p * 16 + rbase, t * 32 + cadd));
                    mma16816h(s[2 * p],     qh[t], KH[0], KH[2]);
                    mma16816h(s[2 * p + 1], qh[t], KH[1], KH[3]);
                }
            }
        }

        // ---- running max + rescale ----
        float rmax0 = -1e30f, rmax1 = -1e30f;
        #pragma unroll
        for (int ni = 0; ni < 8; ni++) {
            rmax0 = fmaxf(rmax0, fmaxf(s[ni][0], s[ni][1]));
            rmax1 = fmaxf(rmax1, fmaxf(s[ni][2], s[ni][3]));
        }
        rmax0 = fmaxf(rmax0, __shfl_xor_sync(0xffffffffu, rmax0, 1));
        rmax0 = fmaxf(rmax0, __shfl_xor_sync(0xffffffffu, rmax0, 2));
        rmax1 = fmaxf(rmax1, __shfl_xor_sync(0xffffffffu, rmax1, 1));
        rmax1 = fmaxf(rmax1, __shfl_xor_sync(0xffffffffu, rmax1, 2));

        const float mn0 = fmaxf(mrow0, rmax0);
        const float mn1 = fmaxf(mrow1, rmax1);
        const float a0 = ex2(mrow0 - mn0);
        const float a1 = ex2(mrow1 - mn1);
        mrow0 = mn0; mrow1 = mn1;

        if (!__all_sync(0xffffffffu, (a0 == 1.0f) && (a1 == 1.0f))) {
            #pragma unroll
            for (int ni = 0; ni < 8; ni++) {
                o[ni][0] *= a0; o[ni][1] *= a0;
                o[ni][2] *= a1; o[ni][3] *= a1;
            }
            lacc[0] *= a0; lacc[1] *= a0;
            lacc[2] *= a1; lacc[3] *= a1;
        }

        // ---- P = exp2(S - mn) in fp16 (f16x2 EX2); O += P V; l += P·1 ----
        #pragma unroll
        for (int t = 0; t < 4; t++) {
            const float* p0 = s[2 * t];
            const float* p1 = s[2 * t + 1];
            uint32_t ah[4];
            ah[0] = hex2(__floats2half2_rn(p0[0] - mn0, p0[1] - mn0));
            ah[1] = hex2(__floats2half2_rn(p0[2] - mn1, p0[3] - mn1));
            ah[2] = hex2(__floats2half2_rn(p1[0] - mn0, p1[1] - mn0));
            ah[3] = hex2(__floats2half2_rn(p1[2] - mn1, p1[3] - mn1));

            const int rr = t * 16 + (lane & 15);
            const int cadd = (lane & 16) ? 16 : 0;
            #pragma unroll
            for (int dp = 0; dp < 4; dp++) {
                uint32_t VH[4];
                ldsm4t(VH, sb + SKV + buf + 8192 + swz(rr, dp * 32 + cadd));
                mma16816h(o[2 * dp],     ah, VH[0], VH[1]);
                mma16816h(o[2 * dp + 1], ah, VH[2], VH[3]);
            }
            mma16816h(lacc, ah, ONES_H2, ONES_H2);
        }

        cp_wait0();
        __syncthreads();
    }

    // ---- normalize + write O as fp16 hi/lo to [B,N,H*d] ----
    {
        const float inv0 = 1.0f / lacc[0];
        const float inv1 = 1.0f / lacc[2];
        const int r0 = q0 + m0 + (lane >> 2);
        const int cb = 2 * (lane & 3);
        const size_t base0 = ((size_t)(b * N_ + r0)) * INNER_ + h * D_;
        const size_t base1 = ((size_t)(b * N_ + r0 + 8)) * INNER_ + h * D_;
        #pragma unroll
        for (int ni = 0; ni < 8; ni++) {
            int dd = ni * 8 + cb;
            {
                float v0 = o[ni][0] * inv0, v1 = o[ni][1] * inv0;
                __half2 hv = __floats2half2_rn(v0, v1);
                float2 hf = __half22float2(hv);
                __half2 lv = __floats2half2_rn(v0 - hf.x, v1 - hf.y);
                *(uint32_t*)&g_ohh[base0 + dd] = u32h2(hv);
                *(uint32_t*)&g_ohl[base0 + dd] = u32h2(lv);
            }
            {
                float v0 = o[ni][2] * inv1, v1 = o[ni][3] * inv1;
                __half2 hv = __floats2half2_rn(v0, v1);
                float2 hf = __half22float2(hv);
                __half2 lv = __floats2half2_rn(v0 - hf.x, v1 - hf.y);
                *(uint32_t*)&g_ohh[base1 + dd] = u32h2(hv);
                *(uint32_t*)&g_ohl[base1 + dd] = u32h2(lv);
            }
        }
    }
}

// ---------------------------------------------------------------------------
extern "C" void kernel_launch(void* const* d_in, const int* in_sizes, int n_in,
                              void* d_out, int out_size)
{
    const float* x     = (const float*)d_in[0];
    const float* pos   = (const float*)d_in[1];
    const float* w_qkv = (const float*)d_in[2];
    const float* w_out = (const float*)d_in[3];
    const float* b_out = (const float*)d_in[4];
    float* out = (float*)d_out;

    static bool attr_set = false;
    if (!attr_set) {
        cudaFuncSetAttribute(flash_mma_kernel,
                             cudaFuncAttributeMaxDynamicSharedMemorySize,
                             SMEM_BYTES);
        cudaFuncSetAttribute(gemm_qkv_mma,
                             cudaFuncAttributeMaxDynamicSharedMemorySize,
                             QSMEM);
        cudaFuncSetAttribute(gemm_out_mma,
                             cudaFuncAttributeMaxDynamicSharedMemorySize,
                             GSMEM);
        attr_set = true;
    }

    conv_all_kernel<<<(N4ALL + 255) / 256, 256>>>(
        (const float4*)x, (const float4*)w_qkv, (const float4*)w_out);

    gemm_qkv_mma<<<dim3(QKVCOLS_ / 128, M_ / 128), 256, QSMEM>>>(pos);

    flash_mma_kernel<<<dim3(N_ / BR, B_ * H_), 256, SMEM_BYTES>>>();

    gemm_out_mma<<<dim3(C_ / 64, M_ / 128), 256, GSMEM>>>(b_out, out);
}

// round 11
// speedup vs baseline: 1.0302x; 1.0302x over previous
#include <cuda_runtime.h>
#include <cuda_bf16.h>
#include <cuda_fp16.h>
#include <cstdint>

// Problem constants
#define B_   2
#define N_   4096
#define C_   512
#define H_   8
#define D_   64
#define INNER_ (H_ * D_)          // 512
#define QKVCOLS_ (INNER_ * 3)     // 1536
#define M_ (B_ * N_)              // 8192
#define R_TOTAL (B_ * H_ * N_)    // 65536 rows of 64

// Scratch (device globals; no cudaMalloc allowed)
__device__ __half g_qh[R_TOTAL * D_];
__device__ __half g_kh[R_TOTAL * D_];
__device__ __half g_vh[R_TOTAL * D_];
__device__ __half g_xh[M_ * C_], g_xl[M_ * C_];
__device__ __half g_wq[C_ * QKVCOLS_];
__device__ __half g_wo[INNER_ * C_];
__device__ __half g_ohh[B_ * N_ * INNER_], g_ohl[B_ * N_ * INNER_];

#define SCALE_LOG2E (0.125f * 1.4426950408889634f)

// ---------------------------------------------------------------------------
// common helpers
// ---------------------------------------------------------------------------
__device__ __forceinline__ uint32_t u32h2(__half2 v)
{
    return reinterpret_cast<uint32_t&>(v);
}
__device__ __forceinline__ float ex2(float x)
{
    float y;
    asm("ex2.approx.ftz.f32 %0, %1;" : "=f"(y) : "f"(x));
    return y;
}
__device__ __forceinline__ uint32_t hex2(__half2 v)
{
    uint32_t y;
    asm("ex2.approx.f16x2 %0, %1;" : "=r"(y) : "r"(u32h2(v)));
    return y;
}
__device__ __forceinline__ float2 h2f2(uint32_t h)
{
    return __half22float2(reinterpret_cast<__half2&>(h));
}
__device__ __forceinline__ uint32_t swz(uint32_t row, uint32_t colb)
{
    uint32_t b = (row << 7) + colb;     // 128B rows
    return b ^ ((b >> 3) & 0x70);
}
__device__ __forceinline__ uint32_t swzA(uint32_t row, uint32_t colb)
{
    uint32_t b = (row << 6) + colb;     // 64B rows
    return b ^ ((b >> 3) & 0x30);
}
__device__ __forceinline__ void cp16(uint32_t dst, const void* src)
{
    asm volatile("cp.async.cg.shared.global [%0], [%1], 16;"
                 :: "r"(dst), "l"(src));
}
__device__ __forceinline__ void cp_commit()
{
    asm volatile("cp.async.commit_group;");
}
__device__ __forceinline__ void cp_wait0()
{
    asm volatile("cp.async.wait_group 0;");
}
__device__ __forceinline__ void cp_wait1()
{
    asm volatile("cp.async.wait_group 1;");
}
__device__ __forceinline__ void ldsm4(uint32_t a[4], uint32_t addr)
{
    asm volatile("ldmatrix.sync.aligned.m8n8.x4.shared.b16 {%0,%1,%2,%3}, [%4];"
                 : "=r"(a[0]), "=r"(a[1]), "=r"(a[2]), "=r"(a[3]) : "r"(addr));
}
__device__ __forceinline__ void ldsm4t(uint32_t a[4], uint32_t addr)
{
    asm volatile("ldmatrix.sync.aligned.m8n8.x4.trans.shared.b16 {%0,%1,%2,%3}, [%4];"
                 : "=r"(a[0]), "=r"(a[1]), "=r"(a[2]), "=r"(a[3]) : "r"(addr));
}
__device__ __forceinline__ void mma16816h(float c[4], const uint32_t a[4],
                                          uint32_t b0, uint32_t b1)
{
    asm volatile(
        "mma.sync.aligned.m16n8k16.row.col.f32.f16.f16.f32 "
        "{%0,%1,%2,%3}, {%4,%5,%6,%7}, {%8,%9}, {%0,%1,%2,%3};"
        : "+f"(c[0]), "+f"(c[1]), "+f"(c[2]), "+f"(c[3])
        : "r"(a[0]), "r"(a[1]), "r"(a[2]), "r"(a[3]), "r"(b0), "r"(b1));
}

// ---------------------------------------------------------------------------
// K0: merged conversion — x -> hi/lo split; w_qkv, w_out -> fp16 single.
// ---------------------------------------------------------------------------
#define N4X  (M_ * C_ / 4)
#define N4WQ (C_ * QKVCOLS_ / 4)
#define N4WO (INNER_ * C_ / 4)
#define N4ALL (N4X + N4WQ + N4WO)

__global__ __launch_bounds__(256) void conv_all_kernel(
    const float4* __restrict__ x, const float4* __restrict__ wq,
    const float4* __restrict__ wo)
{
    int i = blockIdx.x * 256 + threadIdx.x;
    if (i < N4X) {
        float4 f = x[i];
        __half2 h0 = __floats2half2_rn(f.x, f.y);
        __half2 h1 = __floats2half2_rn(f.z, f.w);
        float2 a = __half22float2(h0), b = __half22float2(h1);
        __half2 l0 = __floats2half2_rn(f.x - a.x, f.y - a.y);
        __half2 l1 = __floats2half2_rn(f.z - b.x, f.w - b.y);
        ((uint2*)g_xh)[i] = make_uint2(u32h2(h0), u32h2(h1));
        ((uint2*)g_xl)[i] = make_uint2(u32h2(l0), u32h2(l1));
    } else if (i < N4X + N4WQ) {
        int j = i - N4X;
        float4 f = wq[j];
        ((uint2*)g_wq)[j] = make_uint2(u32h2(__floats2half2_rn(f.x, f.y)),
                                       u32h2(__floats2half2_rn(f.z, f.w)));
    } else if (i < N4ALL) {
        int j = i - N4X - N4WQ;
        float4 f = wo[j];
        ((uint2*)g_wo)[j] = make_uint2(u32h2(__floats2half2_rn(f.x, f.y)),
                                       u32h2(__floats2half2_rn(f.z, f.w)));
    }
}

// ---------------------------------------------------------------------------
// Shared GEMM machinery. BM=128, BN=64, BK=32, 3-stage cp.async, fp16 2-term.
// 8 warps, 8m x 1n layout: warp tile 16x64 (32 accumulator regs).
// ---------------------------------------------------------------------------
#define GSA_H 0
#define GSA_L 8192
#define GSB   16384
#define GSTAGE 20480
#define GSMEM (3 * GSTAGE)   // 61440
#define GNKT (C_ / 32)       // 16

__device__ __forceinline__ void gemm_stage(
    uint32_t sb, uint32_t stg,
    const __half* __restrict__ ah, const __half* __restrict__ al,
    const __half* __restrict__ bw,
    int m0, int n0, int k0, int ldb, int tid)
{
    #pragma unroll
    for (int i = 0; i < 5; i++) {
        int c = tid + i * 256;               // 0..1279
        if (c < 512) {
            int row = c >> 2, col16 = c & 3;
            cp16(sb + stg + GSA_H + swzA(row, col16 * 16),
                 ah + (size_t)(m0 + row) * C_ + k0 + col16 * 8);
        } else if (c < 1024) {
            int cc = c - 512;
            int row = cc >> 2, col16 = cc & 3;
            cp16(sb + stg + GSA_L + swzA(row, col16 * 16),
                 al + (size_t)(m0 + row) * C_ + k0 + col16 * 8);
        } else {
            int cc = c - 1024;               // 0..255
            int row = cc >> 3, col16 = cc & 7;
            cp16(sb + stg + GSB + swz(row, col16 * 16),
                 bw + (size_t)(k0 + row) * ldb + n0 + col16 * 8);
        }
    }
}

// compute one BK=32 slab; c[8][4] covers warp tile 16x64
__device__ __forceinline__ void gemm_compute(
    uint32_t sb, uint32_t stg, float c[8][4], int wid, int lane)
{
    const int rA = lane & 15;
    const int cadd = (lane & 16) ? 16 : 0;
    #pragma unroll
    for (int t = 0; t < 2; t++) {
        uint32_t AH[4], AL[4], BW[4][4];
        {
            uint32_t off = swzA(wid * 16 + rA, t * 32 + cadd);
            ldsm4(AH, sb + stg + GSA_H + off);
            ldsm4(AL, sb + stg + GSA_L + off);
        }
        #pragma unroll
        for (int j2 = 0; j2 < 4; j2++) {
            uint32_t off = swz(t * 16 + rA, j2 * 32 + cadd);
            ldsm4t(BW[j2], sb + stg + GSB + off);
        }
        #pragma unroll
        for (int j2 = 0; j2 < 4; j2++) {
            mma16816h(c[2 * j2],     AH, BW[j2][0], BW[j2][1]);
            mma16816h(c[2 * j2 + 1], AH, BW[j2][2], BW[j2][3]);
            mma16816h(c[2 * j2],     AL, BW[j2][0], BW[j2][1]);
            mma16816h(c[2 * j2 + 1], AL, BW[j2][2], BW[j2][3]);
        }
    }
}

// K1: QKV GEMM. grid (24, 64). Fused epilogue: RoPE + scale(q) + fp16 scatter.
__global__ __launch_bounds__(256) void gemm_qkv_mma(const float* __restrict__ pos)
{
    extern __shared__ char smemq[];
    const uint32_t sb = (uint32_t)__cvta_generic_to_shared(smemq);
    const int tid = threadIdx.x;
    const int wid = tid >> 5, lane = tid & 31;
    const int m0 = blockIdx.y * 128;
    const int n0 = blockIdx.x * 64;

    float c[8][4] = {};

    gemm_stage(sb, 0,      g_xh, g_xl, g_wq, m0, n0, 0,  QKVCOLS_, tid);
    cp_commit();
    gemm_stage(sb, GSTAGE, g_xh, g_xl, g_wq, m0, n0, 32, QKVCOLS_, tid);
    cp_commit();

    for (int kt = 0; kt < GNKT; kt++) {
        if (kt < GNKT - 1) cp_wait1(); else cp_wait0();
        __syncthreads();
        if (kt + 2 < GNKT) {
            gemm_stage(sb, ((kt + 2) % 3) * GSTAGE, g_xh, g_xl, g_wq,
                       m0, n0, (kt + 2) * 32, QKVCOLS_, tid);
            cp_commit();
        }
        gemm_compute(sb, (kt % 3) * GSTAGE, c, wid, lane);
    }

    // fused epilogue: warp n-width = 64 = one head; partner dd^32 == nj^4
    const int part = n0 >> 9;                          // 0=q, 1=k, 2=v
    const int h = (n0 & 511) >> 6;
    __half* dst = (part == 0) ? g_qh : (part == 1) ? g_kh : g_vh;

    #pragma unroll
    for (int r8 = 0; r8 < 2; r8++) {
        const int mrow = m0 + wid * 16 + r8 * 8 + (lane >> 2);
        const int b = mrow >> 12;
        const int n = mrow & (N_ - 1);
        const size_t base = ((size_t)(b * H_ + h) * N_ + n) * D_;
        #pragma unroll
        for (int nj = 0; nj < 8; nj++) {
            const int dd = nj * 8 + (lane & 3) * 2;
            float v0 = c[nj][2 * r8];
            float v1 = c[nj][2 * r8 + 1];
            float r0, r1;
            if (part < 2) {
                float s0, c0, s1, c1;
                __sincosf(pos[n * D_ + dd],     &s0, &c0);
                __sincosf(pos[n * D_ + dd + 1], &s1, &c1);
                const float q0 = c[nj ^ 4][2 * r8];
                const float q1 = c[nj ^ 4][2 * r8 + 1];
                const float sign = (nj < 4) ? -1.0f : 1.0f;
                r0 = v0 * c0 + sign * q0 * s0;
                r1 = v1 * c1 + sign * q1 * s1;
                if (part == 0) { r0 *= SCALE_LOG2E; r1 *= SCALE_LOG2E; }
            } else {
                r0 = v0; r1 = v1;
            }
            *(uint32_t*)&dst[base + dd] = u32h2(__floats2half2_rn(r0, r1));
        }
    }
}

// K4: output GEMM. grid (8, 64).
__global__ __launch_bounds__(256) void gemm_out_mma(
    const float* __restrict__ bias, float* __restrict__ out)
{
    extern __shared__ char smemo[];
    const uint32_t sb = (uint32_t)__cvta_generic_to_shared(smemo);
    const int tid = threadIdx.x;
    const int wid = tid >> 5, lane = tid & 31;
    const int m0 = blockIdx.y * 128;
    const int n0 = blockIdx.x * 64;

    float c[8][4] = {};

    gemm_stage(sb, 0,      g_ohh, g_ohl, g_wo, m0, n0, 0,  C_, tid);
    cp_commit();
    gemm_stage(sb, GSTAGE, g_ohh, g_ohl, g_wo, m0, n0, 32, C_, tid);
    cp_commit();

    for (int kt = 0; kt < GNKT; kt++) {
        if (kt < GNKT - 1) cp_wait1(); else cp_wait0();
        __syncthreads();
        if (kt + 2 < GNKT) {
            gemm_stage(sb, ((kt + 2) % 3) * GSTAGE, g_ohh, g_ohl, g_wo,
                       m0, n0, (kt + 2) * 32, C_, tid);
            cp_commit();
        }
        gemm_compute(sb, (kt % 3) * GSTAGE, c, wid, lane);
    }

    #pragma unroll
    for (int r8 = 0; r8 < 2; r8++) {
        const int mrow = m0 + wid * 16 + r8 * 8 + (lane >> 2);
        #pragma unroll
        for (int nj = 0; nj < 8; nj++) {
            const int col = n0 + nj * 8 + (lane & 3) * 2;
            *(float2*)&out[(size_t)mrow * C_ + col] =
                make_float2(c[nj][2 * r8] + bias[col],
                            c[nj][2 * r8 + 1] + bias[col + 1]);
        }
    }
}

// ---------------------------------------------------------------------------
// K3: flash attention, fp16 mma.sync, BC=64, f16x2 exp, fp32 l from fp16 P.
// ---------------------------------------------------------------------------
#define BR 128
#define BC 64
#define NT (N_ / BC)       // 64

#define SQ    0
#define SKV   16384        // + stage*16384 ; K at +0, V at +8192
#define SMEM_BYTES 49152

__global__ __launch_bounds__(256, 2) void flash_mma_kernel()
{
    extern __shared__ char smraw[];
    const uint32_t sb = (uint32_t)__cvta_generic_to_shared(smraw);

    const int tid = threadIdx.x;
    const int wid = tid >> 5;
    const int lane = tid & 31;
    const int bh = blockIdx.y;
    const int b = bh >> 3, h = bh & 7;
    const int q0 = blockIdx.x * BR;

    // ---- stage Q ----
    {
        const size_t qbase = ((size_t)bh * N_ + q0) * D_;
        #pragma unroll
        for (int i = 0; i < 4; i++) {
            int c = tid + i * 256;
            int row = c >> 3;
            int col16 = c & 7;
            cp16(sb + SQ + swz(row, col16 * 16),
                 g_qh + qbase + (size_t)row * D_ + col16 * 8);
        }
    }
    // ---- stage KV tile 0 ----
    {
        const size_t kvbase = (size_t)bh * N_ * D_;
        #pragma unroll
        for (int i = 0; i < 4; i++) {
            int c = tid + i * 256;
            int arr = c >> 9;
            int cc = c & 511;
            int row = cc >> 3;
            int col16 = cc & 7;
            cp16(sb + SKV + (arr ? 8192 : 0) + swz(row, col16 * 16),
                 (arr ? g_vh : g_kh) + kvbase + (size_t)row * D_ + col16 * 8);
        }
    }
    cp_commit();
    cp_wait0();
    __syncthreads();

    // ---- Q fragments (registers, whole kernel) ----
    const int m0 = wid * 16;
    uint32_t qh[4][4];
    {
        int r = m0 + (lane & 15);
        int cadd = (lane & 16) ? 16 : 0;
        #pragma unroll
        for (int t = 0; t < 4; t++)
            ldsm4(qh[t], sb + SQ + swz(r, t * 32 + cadd));
    }

    float o[8][4] = {};
    float mrow0 = -1e30f, mrow1 = -1e30f;
    float lrow0 = 0.f, lrow1 = 0.f;

    const size_t kvstride = (size_t)bh * N_ * D_;

    for (int kt = 0; kt < NT; kt++) {
        const uint32_t buf = (kt & 1) ? 16384 : 0;
        const uint32_t nbuf = (kt & 1) ? 0 : 16384;

        if (kt + 1 < NT) {
            const size_t kvbase = kvstride + (size_t)(kt + 1) * BC * D_;
            #pragma unroll
            for (int i = 0; i < 4; i++) {
                int c = tid + i * 256;
                int arr = c >> 9;
                int cc = c & 511;
                int row = cc >> 3;
                int col16 = cc & 7;
                cp16(sb + SKV + nbuf + (arr ? 8192 : 0) + swz(row, col16 * 16),
                     (arr ? g_vh : g_kh) + kvbase + (size_t)row * D_ + col16 * 8);
            }
            cp_commit();
        }

        // ---- S = Q K^T (fp32 accum) ----
        float s[8][4] = {};
        {
            const int rbase = lane & 15;
            const int cadd = (lane & 16) ? 16 : 0;
            #pragma unroll
            for (int p = 0; p < 4; p++) {
                #pragma unroll
                for (int t = 0; t < 4; t++) {
                    uint32_t KH[4];
                    ldsm4(KH, sb + SKV + buf + swz(p * 16 + rbase, t * 32 + cadd));
                    mma16816h(s[2 * p],     qh[t], KH[0], KH[2]);
                    mma16816h(s[2 * p + 1], qh[t], KH[1], KH[3]);
                }
            }
        }

        // ---- running max + unconditional rescale ----
        float rmax0 = -1e30f, rmax1 = -1e30f;
        #pragma unroll
        for (int ni = 0; ni < 8; ni++) {
            rmax0 = fmaxf(rmax0, fmaxf(s[ni][0], s[ni][1]));
            rmax1 = fmaxf(rmax1, fmaxf(s[ni][2], s[ni][3]));
        }
        rmax0 = fmaxf(rmax0, __shfl_xor_sync(0xffffffffu, rmax0, 1));
        rmax0 = fmaxf(rmax0, __shfl_xor_sync(0xffffffffu, rmax0, 2));
        rmax1 = fmaxf(rmax1, __shfl_xor_sync(0xffffffffu, rmax1, 1));
        rmax1 = fmaxf(rmax1, __shfl_xor_sync(0xffffffffu, rmax1, 2));

        const float mn0 = fmaxf(mrow0, rmax0);
        const float mn1 = fmaxf(mrow1, rmax1);
        const float a0 = ex2(mrow0 - mn0);
        const float a1 = ex2(mrow1 - mn1);
        mrow0 = mn0; mrow1 = mn1;

        #pragma unroll
        for (int ni = 0; ni < 8; ni++) {
            o[ni][0] *= a0; o[ni][1] *= a0;
            o[ni][2] *= a1; o[ni][3] *= a1;
        }

        // ---- P = exp2(S-mn) in fp16; O += P V; l += sum(P) in fp32 ----
        float sum0 = 0.f, sum1 = 0.f;
        #pragma unroll
        for (int t = 0; t < 4; t++) {
            const float* p0 = s[2 * t];
            const float* p1 = s[2 * t + 1];
            uint32_t ah[4];
            ah[0] = hex2(__floats2half2_rn(p0[0] - mn0, p0[1] - mn0));
            ah[1] = hex2(__floats2half2_rn(p0[2] - mn1, p0[3] - mn1));
            ah[2] = hex2(__floats2half2_rn(p1[0] - mn0, p1[1] - mn0));
            ah[3] = hex2(__floats2half2_rn(p1[2] - mn1, p1[3] - mn1));

            float2 f0 = h2f2(ah[0]), f1 = h2f2(ah[1]);
            float2 f2 = h2f2(ah[2]), f3 = h2f2(ah[3]);
            sum0 += (f0.x + f0.y) + (f2.x + f2.y);
            sum1 += (f1.x + f1.y) + (f3.x + f3.y);

            const int rr = t * 16 + (lane & 15);
            const int cadd = (lane & 16) ? 16 : 0;
            #pragma unroll
            for (int dp = 0; dp < 4; dp++) {
                uint32_t VH[4];
                ldsm4t(VH, sb + SKV + buf + 8192 + swz(rr, dp * 32 + cadd));
                mma16816h(o[2 * dp],     ah, VH[0], VH[1]);
                mma16816h(o[2 * dp + 1], ah, VH[2], VH[3]);
            }
        }
        sum0 += __shfl_xor_sync(0xffffffffu, sum0, 1);
        sum0 += __shfl_xor_sync(0xffffffffu, sum0, 2);
        sum1 += __shfl_xor_sync(0xffffffffu, sum1, 1);
        sum1 += __shfl_xor_sync(0xffffffffu, sum1, 2);
        lrow0 = lrow0 * a0 + sum0;
        lrow1 = lrow1 * a1 + sum1;

        cp_wait0();
        __syncthreads();
    }

    // ---- normalize + write O as fp16 hi/lo to [B,N,H*d] ----
    {
        const float inv0 = 1.0f / lrow0;
        const float inv1 = 1.0f / lrow1;
        const int r0 = q0 + m0 + (lane >> 2);
        const int cb = 2 * (lane & 3);
        const size_t base0 = ((size_t)(b * N_ + r0)) * INNER_ + h * D_;
        const size_t base1 = ((size_t)(b * N_ + r0 + 8)) * INNER_ + h * D_;
        #pragma unroll
        for (int ni = 0; ni < 8; ni++) {
            int dd = ni * 8 + cb;
            {
                float v0 = o[ni][0] * inv0, v1 = o[ni][1] * inv0;
                __half2 hv = __floats2half2_rn(v0, v1);
                float2 hf = __half22float2(hv);
                __half2 lv = __floats2half2_rn(v0 - hf.x, v1 - hf.y);
                *(uint32_t*)&g_ohh[base0 + dd] = u32h2(hv);
                *(uint32_t*)&g_ohl[base0 + dd] = u32h2(lv);
            }
            {
                float v0 = o[ni][2] * inv1, v1 = o[ni][3] * inv1;
                __half2 hv = __floats2half2_rn(v0, v1);
                float2 hf = __half22float2(hv);
                __half2 lv = __floats2half2_rn(v0 - hf.x, v1 - hf.y);
                *(uint32_t*)&g_ohh[base1 + dd] = u32h2(hv);
                *(uint32_t*)&g_ohl[base1 + dd] = u32h2(lv);
            }
        }
    }
}

// ---------------------------------------------------------------------------
extern "C" void kernel_launch(void* const* d_in, const int* in_sizes, int n_in,
                              void* d_out, int out_size)
{
    const float* x     = (const float*)d_in[0];
    const float* pos   = (const float*)d_in[1];
    const float* w_qkv = (const float*)d_in[2];
    const float* w_out = (const float*)d_in[3];
    const float* b_out = (const float*)d_in[4];
    float* out = (float*)d_out;

    static bool attr_set = false;
    if (!attr_set) {
        cudaFuncSetAttribute(flash_mma_kernel,
                             cudaFuncAttributeMaxDynamicSharedMemorySize,
                             SMEM_BYTES);
        cudaFuncSetAttribute(gemm_qkv_mma,
                             cudaFuncAttributeMaxDynamicSharedMemorySize,
                             GSMEM);
        cudaFuncSetAttribute(gemm_out_mma,
                             cudaFuncAttributeMaxDynamicSharedMemorySize,
                             GSMEM);
        attr_set = true;
    }

    conv_all_kernel<<<(N4ALL + 255) / 256, 256>>>(
        (const float4*)x, (const float4*)w_qkv, (const float4*)w_out);

    gemm_qkv_mma<<<dim3(QKVCOLS_ / 64, M_ / 128), 256, GSMEM>>>(pos);

    flash_mma_kernel<<<dim3(N_ / BR, B_ * H_), 256, SMEM_BYTES>>>();

    gemm_out_mma<<<dim3(C_ / 64, M_ / 128), 256, GSMEM>>>(b_out, out);
}

// round 13
// speedup vs baseline: 1.0367x; 1.0063x over previous
#include <cuda_runtime.h>
#include <cuda_bf16.h>
#include <cuda_fp16.h>
#include <cstdint>

// Problem constants
#define B_   2
#define N_   4096
#define C_   512
#define H_   8
#define D_   64
#define INNER_ (H_ * D_)          // 512
#define QKVCOLS_ (INNER_ * 3)     // 1536
#define M_ (B_ * N_)              // 8192
#define R_TOTAL (B_ * H_ * N_)    // 65536 rows of 64

// Scratch (device globals; no cudaMalloc allowed)
__device__ __half g_qh[R_TOTAL * D_];
__device__ __half g_kh[R_TOTAL * D_];
__device__ __half g_vh[R_TOTAL * D_];
__device__ __half g_xh[M_ * C_], g_xl[M_ * C_];
__device__ __half g_wq[C_ * QKVCOLS_];
__device__ __half g_wo[INNER_ * C_];
__device__ __half g_ohh[B_ * N_ * INNER_], g_ohl[B_ * N_ * INNER_];

#define SCALE_LOG2E (0.125f * 1.4426950408889634f)

// ---------------------------------------------------------------------------
// common helpers
// ---------------------------------------------------------------------------
__device__ __forceinline__ uint32_t u32h2(__half2 v)
{
    return reinterpret_cast<uint32_t&>(v);
}
__device__ __forceinline__ float ex2(float x)
{
    float y;
    asm("ex2.approx.ftz.f32 %0, %1;" : "=f"(y) : "f"(x));
    return y;
}
__device__ __forceinline__ uint32_t hex2(__half2 v)
{
    uint32_t y;
    asm("ex2.approx.f16x2 %0, %1;" : "=r"(y) : "r"(u32h2(v)));
    return y;
}
__device__ __forceinline__ float2 h2f2(uint32_t h)
{
    return __half22float2(reinterpret_cast<__half2&>(h));
}
__device__ __forceinline__ uint32_t swz(uint32_t row, uint32_t colb)
{
    uint32_t b = (row << 7) + colb;     // 128B rows
    return b ^ ((b >> 3) & 0x70);
}
__device__ __forceinline__ uint32_t swzA(uint32_t row, uint32_t colb)
{
    uint32_t b = (row << 6) + colb;     // 64B rows
    return b ^ ((b >> 3) & 0x30);
}
__device__ __forceinline__ void cp16(uint32_t dst, const void* src)
{
    asm volatile("cp.async.cg.shared.global [%0], [%1], 16;"
                 :: "r"(dst), "l"(src));
}
__device__ __forceinline__ void cp_commit()
{
    asm volatile("cp.async.commit_group;");
}
__device__ __forceinline__ void cp_wait0()
{
    asm volatile("cp.async.wait_group 0;");
}
__device__ __forceinline__ void cp_wait1()
{
    asm volatile("cp.async.wait_group 1;");
}
__device__ __forceinline__ void ldsm4(uint32_t a[4], uint32_t addr)
{
    asm volatile("ldmatrix.sync.aligned.m8n8.x4.shared.b16 {%0,%1,%2,%3}, [%4];"
                 : "=r"(a[0]), "=r"(a[1]), "=r"(a[2]), "=r"(a[3]) : "r"(addr));
}
__device__ __forceinline__ void ldsm4t(uint32_t a[4], uint32_t addr)
{
    asm volatile("ldmatrix.sync.aligned.m8n8.x4.trans.shared.b16 {%0,%1,%2,%3}, [%4];"
                 : "=r"(a[0]), "=r"(a[1]), "=r"(a[2]), "=r"(a[3]) : "r"(addr));
}
__device__ __forceinline__ void mma16816h(float c[4], const uint32_t a[4],
                                          uint32_t b0, uint32_t b1)
{
    asm volatile(
        "mma.sync.aligned.m16n8k16.row.col.f32.f16.f16.f32 "
        "{%0,%1,%2,%3}, {%4,%5,%6,%7}, {%8,%9}, {%0,%1,%2,%3};"
        : "+f"(c[0]), "+f"(c[1]), "+f"(c[2]), "+f"(c[3])
        : "r"(a[0]), "r"(a[1]), "r"(a[2]), "r"(a[3]), "r"(b0), "r"(b1));
}

// ---------------------------------------------------------------------------
// K0: merged conversion — x -> hi/lo split; w_qkv, w_out -> fp16 single.
// ---------------------------------------------------------------------------
#define N4X  (M_ * C_ / 4)
#define N4WQ (C_ * QKVCOLS_ / 4)
#define N4WO (INNER_ * C_ / 4)
#define N4ALL (N4X + N4WQ + N4WO)

__global__ __launch_bounds__(256) void conv_all_kernel(
    const float4* __restrict__ x, const float4* __restrict__ wq,
    const float4* __restrict__ wo)
{
    int i = blockIdx.x * 256 + threadIdx.x;
    if (i < N4X) {
        float4 f = x[i];
        __half2 h0 = __floats2half2_rn(f.x, f.y);
        __half2 h1 = __floats2half2_rn(f.z, f.w);
        float2 a = __half22float2(h0), b = __half22float2(h1);
        __half2 l0 = __floats2half2_rn(f.x - a.x, f.y - a.y);
        __half2 l1 = __floats2half2_rn(f.z - b.x, f.w - b.y);
        ((uint2*)g_xh)[i] = make_uint2(u32h2(h0), u32h2(h1));
        ((uint2*)g_xl)[i] = make_uint2(u32h2(l0), u32h2(l1));
    } else if (i < N4X + N4WQ) {
        int j = i - N4X;
        float4 f = wq[j];
        ((uint2*)g_wq)[j] = make_uint2(u32h2(__floats2half2_rn(f.x, f.y)),
                                       u32h2(__floats2half2_rn(f.z, f.w)));
    } else if (i < N4ALL) {
        int j = i - N4X - N4WQ;
        float4 f = wo[j];
        ((uint2*)g_wo)[j] = make_uint2(u32h2(__floats2half2_rn(f.x, f.y)),
                                       u32h2(__floats2half2_rn(f.z, f.w)));
    }
}

// ---------------------------------------------------------------------------
// Shared GEMM machinery (Round-11, known good). BM=128, BN=64, BK=32,
// 3-stage cp.async, fp16 2-term. 8 warps, 8m x 1n (warp tile 16x64).
// ---------------------------------------------------------------------------
#define GSA_H 0
#define GSA_L 8192
#define GSB   16384
#define GSTAGE 20480
#define GSMEM (3 * GSTAGE)   // 61440
#define GNKT (C_ / 32)       // 16

__device__ __forceinline__ void gemm_stage(
    uint32_t sb, uint32_t stg,
    const __half* __restrict__ ah, const __half* __restrict__ al,
    const __half* __restrict__ bw,
    int m0, int n0, int k0, int ldb, int tid)
{
    #pragma unroll
    for (int i = 0; i < 5; i++) {
        int c = tid + i * 256;               // 0..1279
        if (c < 512) {
            int row = c >> 2, col16 = c & 3;
            cp16(sb + stg + GSA_H + swzA(row, col16 * 16),
                 ah + (size_t)(m0 + row) * C_ + k0 + col16 * 8);
        } else if (c < 1024) {
            int cc = c - 512;
            int row = cc >> 2, col16 = cc & 3;
            cp16(sb + stg + GSA_L + swzA(row, col16 * 16),
                 al + (size_t)(m0 + row) * C_ + k0 + col16 * 8);
        } else {
            int cc = c - 1024;               // 0..255
            int row = cc >> 3, col16 = cc & 7;
            cp16(sb + stg + GSB + swz(row, col16 * 16),
                 bw + (size_t)(k0 + row) * ldb + n0 + col16 * 8);
        }
    }
}

__device__ __forceinline__ void gemm_compute(
    uint32_t sb, uint32_t stg, float c[8][4], int wid, int lane)
{
    const int rA = lane & 15;
    const int cadd = (lane & 16) ? 16 : 0;
    #pragma unroll
    for (int t = 0; t < 2; t++) {
        uint32_t AH[4], AL[4], BW[4][4];
        {
            uint32_t off = swzA(wid * 16 + rA, t * 32 + cadd);
            ldsm4(AH, sb + stg + GSA_H + off);
            ldsm4(AL, sb + stg + GSA_L + off);
        }
        #pragma unroll
        for (int j2 = 0; j2 < 4; j2++) {
            uint32_t off = swz(t * 16 + rA, j2 * 32 + cadd);
            ldsm4t(BW[j2], sb + stg + GSB + off);
        }
        #pragma unroll
        for (int j2 = 0; j2 < 4; j2++) {
            mma16816h(c[2 * j2],     AH, BW[j2][0], BW[j2][1]);
            mma16816h(c[2 * j2 + 1], AH, BW[j2][2], BW[j2][3]);
            mma16816h(c[2 * j2],     AL, BW[j2][0], BW[j2][1]);
            mma16816h(c[2 * j2 + 1], AL, BW[j2][2], BW[j2][3]);
        }
    }
}

// K1: QKV GEMM. grid (24, 64). Fused epilogue: RoPE + scale(q) + fp16 scatter.
__global__ __launch_bounds__(256) void gemm_qkv_mma(const float* __restrict__ pos)
{
    extern __shared__ char smemq[];
    const uint32_t sb = (uint32_t)__cvta_generic_to_shared(smemq);
    const int tid = threadIdx.x;
    const int wid = tid >> 5, lane = tid & 31;
    const int m0 = blockIdx.y * 128;
    const int n0 = blockIdx.x * 64;

    float c[8][4] = {};

    gemm_stage(sb, 0,      g_xh, g_xl, g_wq, m0, n0, 0,  QKVCOLS_, tid);
    cp_commit();
    gemm_stage(sb, GSTAGE, g_xh, g_xl, g_wq, m0, n0, 32, QKVCOLS_, tid);
    cp_commit();

    for (int kt = 0; kt < GNKT; kt++) {
        if (kt < GNKT - 1) cp_wait1(); else cp_wait0();
        __syncthreads();
        if (kt + 2 < GNKT) {
            gemm_stage(sb, ((kt + 2) % 3) * GSTAGE, g_xh, g_xl, g_wq,
                       m0, n0, (kt + 2) * 32, QKVCOLS_, tid);
            cp_commit();
        }
        gemm_compute(sb, (kt % 3) * GSTAGE, c, wid, lane);
    }

    const int part = n0 >> 9;                          // 0=q, 1=k, 2=v
    const int h = (n0 & 511) >> 6;
    __half* dst = (part == 0) ? g_qh : (part == 1) ? g_kh : g_vh;

    #pragma unroll
    for (int r8 = 0; r8 < 2; r8++) {
        const int mrow = m0 + wid * 16 + r8 * 8 + (lane >> 2);
        const int b = mrow >> 12;
        const int n = mrow & (N_ - 1);
        const size_t base = ((size_t)(b * H_ + h) * N_ + n) * D_;
        #pragma unroll
        for (int nj = 0; nj < 8; nj++) {
            const int dd = nj * 8 + (lane & 3) * 2;
            float v0 = c[nj][2 * r8];
            float v1 = c[nj][2 * r8 + 1];
            float r0, r1;
            if (part < 2) {
                float s0, c0, s1, c1;
                __sincosf(pos[n * D_ + dd],     &s0, &c0);
                __sincosf(pos[n * D_ + dd + 1], &s1, &c1);
                const float q0 = c[nj ^ 4][2 * r8];
                const float q1 = c[nj ^ 4][2 * r8 + 1];
                const float sign = (nj < 4) ? -1.0f : 1.0f;
                r0 = v0 * c0 + sign * q0 * s0;
                r1 = v1 * c1 + sign * q1 * s1;
                if (part == 0) { r0 *= SCALE_LOG2E; r1 *= SCALE_LOG2E; }
            } else {
                r0 = v0; r1 = v1;
            }
            *(uint32_t*)&dst[base + dd] = u32h2(__floats2half2_rn(r0, r1));
        }
    }
}

// K4: output GEMM. grid (8, 64).
__global__ __launch_bounds__(256) void gemm_out_mma(
    const float* __restrict__ bias, float* __restrict__ out)
{
    extern __shared__ char smemo[];
    const uint32_t sb = (uint32_t)__cvta_generic_to_shared(smemo);
    const int tid = threadIdx.x;
    const int wid = tid >> 5, lane = tid & 31;
    const int m0 = blockIdx.y * 128;
    const int n0 = blockIdx.x * 64;

    float c[8][4] = {};

    gemm_stage(sb, 0,      g_ohh, g_ohl, g_wo, m0, n0, 0,  C_, tid);
    cp_commit();
    gemm_stage(sb, GSTAGE, g_ohh, g_ohl, g_wo, m0, n0, 32, C_, tid);
    cp_commit();

    for (int kt = 0; kt < GNKT; kt++) {
        if (kt < GNKT - 1) cp_wait1(); else cp_wait0();
        __syncthreads();
        if (kt + 2 < GNKT) {
            gemm_stage(sb, ((kt + 2) % 3) * GSTAGE, g_ohh, g_ohl, g_wo,
                       m0, n0, (kt + 2) * 32, C_, tid);
            cp_commit();
        }
        gemm_compute(sb, (kt % 3) * GSTAGE, c, wid, lane);
    }

    #pragma unroll
    for (int r8 = 0; r8 < 2; r8++) {
        const int mrow = m0 + wid * 16 + r8 * 8 + (lane >> 2);
        #pragma unroll
        for (int nj = 0; nj < 8; nj++) {
            const int col = n0 + nj * 8 + (lane & 3) * 2;
            *(float2*)&out[(size_t)mrow * C_ + col] =
                make_float2(c[nj][2 * r8] + bias[col],
                            c[nj][2 * r8 + 1] + bias[col + 1]);
        }
    }
}

// ---------------------------------------------------------------------------
// K3: flash attention, BR=256 (warp = 32 q-rows, 2 m16 groups).
// Each K/V ldsm fragment feeds BOTH q-groups -> smem traffic per MAC halved.
// ---------------------------------------------------------------------------
#define BR 256
#define BC 64
#define NT (N_ / BC)       // 64

#define SQ    0            // 32 KB
#define SKV   32768        // + stage*16384 ; K at +0, V at +8192
#define SMEM_BYTES 65536

__global__ __launch_bounds__(256, 1) void flash_mma_kernel()
{
    extern __shared__ char smraw[];
    const uint32_t sb = (uint32_t)__cvta_generic_to_shared(smraw);

    const int tid = threadIdx.x;
    const int wid = tid >> 5;
    const int lane = tid & 31;
    const int bh = blockIdx.y;
    const int b = bh >> 3, h = bh & 7;
    const int q0 = blockIdx.x * BR;

    // ---- stage Q (256 rows) ----
    {
        const size_t qbase = ((size_t)bh * N_ + q0) * D_;
        #pragma unroll
        for (int i = 0; i < 8; i++) {
            int c = tid + i * 256;            // 0..2047
            int row = c >> 3;
            int col16 = c & 7;
            cp16(sb + SQ + swz(row, col16 * 16),
                 g_qh + qbase + (size_t)row * D_ + col16 * 8);
        }
    }
    // ---- stage KV tile 0 ----
    {
        const size_t kvbase = (size_t)bh * N_ * D_;
        #pragma unroll
        for (int i = 0; i < 4; i++) {
            int c = tid + i * 256;            // 0..1023
            int arr = c >> 9;                 // 0=K, 1=V
            int cc = c & 511;
            int row = cc >> 3;
            int col16 = cc & 7;
            cp16(sb + SKV + (arr ? 8192 : 0) + swz(row, col16 * 16),
                 (arr ? g_vh : g_kh) + kvbase + (size_t)row * D_ + col16 * 8);
        }
    }
    cp_commit();
    cp_wait0();
    __syncthreads();

    // ---- Q fragments: 2 groups x 4 k-chunks ----
    const int m0 = wid * 32;
    uint32_t qh[2][4][4];
    {
        const int cadd = (lane & 16) ? 16 : 0;
        #pragma unroll
        for (int g = 0; g < 2; g++) {
            int r = m0 + g * 16 + (lane & 15);
            #pragma unroll
            for (int t = 0; t < 4; t++)
                ldsm4(qh[g][t], sb + SQ + swz(r, t * 32 + cadd));
        }
    }

    float o[2][8][4] = {};
    float mrow[2][2] = {{-1e30f, -1e30f}, {-1e30f, -1e30f}};
    float lrow[2][2] = {};

    const size_t kvstride = (size_t)bh * N_ * D_;

    for (int kt = 0; kt < NT; kt++) {
        const uint32_t buf = (kt & 1) ? 16384 : 0;
        const uint32_t nbuf = (kt & 1) ? 0 : 16384;

        if (kt + 1 < NT) {
            const size_t kvbase = kvstride + (size_t)(kt + 1) * BC * D_;
            #pragma unroll
            for (int i = 0; i < 4; i++) {
                int c = tid + i * 256;
                int arr = c >> 9;
                int cc = c & 511;
                int row = cc >> 3;
                int col16 = cc & 7;
                cp16(sb + SKV + nbuf + (arr ? 8192 : 0) + swz(row, col16 * 16),
                     (arr ? g_vh : g_kh) + kvbase + (size_t)row * D_ + col16 * 8);
            }
            cp_commit();
        }

        // ---- S = Q K^T : each K fragment shared across both q-groups ----
        float s[2][8][4] = {};
        {
            const int rbase = lane & 15;
            const int cadd = (lane & 16) ? 16 : 0;
            #pragma unroll
            for (int p = 0; p < 4; p++) {
                #pragma unroll
                for (int t = 0; t < 4; t++) {
                    uint32_t KH[4];
                    ldsm4(KH, sb + SKV + buf + swz(p * 16 + rbase, t * 32 + cadd));
                    #pragma unroll
                    for (int g = 0; g < 2; g++) {
                        mma16816h(s[g][2 * p],     qh[g][t], KH[0], KH[2]);
                        mma16816h(s[g][2 * p + 1], qh[g][t], KH[1], KH[3]);
                    }
                }
            }
        }

        // ---- online softmax per group ----
        float mn[2][2], al[2][2];
        #pragma unroll
        for (int g = 0; g < 2; g++) {
            float rmax0 = -1e30f, rmax1 = -1e30f;
            #pragma unroll
            for (int ni = 0; ni < 8; ni++) {
                rmax0 = fmaxf(rmax0, fmaxf(s[g][ni][0], s[g][ni][1]));
                rmax1 = fmaxf(rmax1, fmaxf(s[g][ni][2], s[g][ni][3]));
            }
            rmax0 = fmaxf(rmax0, __shfl_xor_sync(0xffffffffu, rmax0, 1));
            rmax0 = fmaxf(rmax0, __shfl_xor_sync(0xffffffffu, rmax0, 2));
            rmax1 = fmaxf(rmax1, __shfl_xor_sync(0xffffffffu, rmax1, 1));
            rmax1 = fmaxf(rmax1, __shfl_xor_sync(0xffffffffu, rmax1, 2));

            mn[g][0] = fmaxf(mrow[g][0], rmax0);
            mn[g][1] = fmaxf(mrow[g][1], rmax1);
            al[g][0] = ex2(mrow[g][0] - mn[g][0]);
            al[g][1] = ex2(mrow[g][1] - mn[g][1]);
            mrow[g][0] = mn[g][0]; mrow[g][1] = mn[g][1];

            #pragma unroll
            for (int ni = 0; ni < 8; ni++) {
                o[g][ni][0] *= al[g][0]; o[g][ni][1] *= al[g][0];
                o[g][ni][2] *= al[g][1]; o[g][ni][3] *= al[g][1];
            }
        }

        // ---- P=exp2(S-mn) fp16; O += P V (V fragments shared); l += sum(P)
        float sum[2][2] = {};
        #pragma unroll
        for (int t = 0; t < 4; t++) {
            uint32_t ah[2][4];
            #pragma unroll
            for (int g = 0; g < 2; g++) {
                const float* p0 = s[g][2 * t];
                const float* p1 = s[g][2 * t + 1];
                ah[g][0] = hex2(__floats2half2_rn(p0[0] - mn[g][0],
                                                  p0[1] - mn[g][0]));
                ah[g][1] = hex2(__floats2half2_rn(p0[2] - mn[g][1],
                                                  p0[3] - mn[g][1]));
                ah[g][2] = hex2(__floats2half2_rn(p1[0] - mn[g][0],
                                                  p1[1] - mn[g][0]));
                ah[g][3] = hex2(__floats2half2_rn(p1[2] - mn[g][1],
                                                  p1[3] - mn[g][1]));
                float2 f0 = h2f2(ah[g][0]), f1 = h2f2(ah[g][1]);
                float2 f2 = h2f2(ah[g][2]), f3 = h2f2(ah[g][3]);
                sum[g][0] += (f0.x + f0.y) + (f2.x + f2.y);
                sum[g][1] += (f1.x + f1.y) + (f3.x + f3.y);
            }
            const int rr = t * 16 + (lane & 15);
            const int cadd = (lane & 16) ? 16 : 0;
            #pragma unroll
            for (int dp = 0; dp < 4; dp++) {
                uint32_t VH[4];
                ldsm4t(VH, sb + SKV + buf + 8192 + swz(rr, dp * 32 + cadd));
                #pragma unroll
                for (int g = 0; g < 2; g++) {
                    mma16816h(o[g][2 * dp],     ah[g], VH[0], VH[1]);
                    mma16816h(o[g][2 * dp + 1], ah[g], VH[2], VH[3]);
                }
            }
        }
        #pragma unroll
        for (int g = 0; g < 2; g++) {
            sum[g][0] += __shfl_xor_sync(0xffffffffu, sum[g][0], 1);
            sum[g][0] += __shfl_xor_sync(0xffffffffu, sum[g][0], 2);
            sum[g][1] += __shfl_xor_sync(0xffffffffu, sum[g][1], 1);
            sum[g][1] += __shfl_xor_sync(0xffffffffu, sum[g][1], 2);
            lrow[g][0] = lrow[g][0] * al[g][0] + sum[g][0];
            lrow[g][1] = lrow[g][1] * al[g][1] + sum[g][1];
        }

        cp_wait0();
        __syncthreads();
    }

    // ---- normalize + write O as fp16 hi/lo to [B,N,H*d] ----
    #pragma unroll
    for (int g = 0; g < 2; g++) {
        const float inv0 = 1.0f / lrow[g][0];
        const float inv1 = 1.0f / lrow[g][1];
        const int r0 = q0 + m0 + g * 16 + (lane >> 2);
        const int cb = 2 * (lane & 3);
        const size_t base0 = ((size_t)(b * N_ + r0)) * INNER_ + h * D_;
        const size_t base1 = ((size_t)(b * N_ + r0 + 8)) * INNER_ + h * D_;
        #pragma unroll
        for (int ni = 0; ni < 8; ni++) {
            int dd = ni * 8 + cb;
            {
                float v0 = o[g][ni][0] * inv0, v1 = o[g][ni][1] * inv0;
                __half2 hv = __floats2half2_rn(v0, v1);
                float2 hf = __half22float2(hv);
                __half2 lv = __floats2half2_rn(v0 - hf.x, v1 - hf.y);
                *(uint32_t*)&g_ohh[base0 + dd] = u32h2(hv);
                *(uint32_t*)&g_ohl[base0 + dd] = u32h2(lv);
            }
            {
                float v0 = o[g][ni][2] * inv1, v1 = o[g][ni][3] * inv1;
                __half2 hv = __floats2half2_rn(v0, v1);
                float2 hf = __half22float2(hv);
                __half2 lv = __floats2half2_rn(v0 - hf.x, v1 - hf.y);
                *(uint32_t*)&g_ohh[base1 + dd] = u32h2(hv);
                *(uint32_t*)&g_ohl[base1 + dd] = u32h2(lv);
            }
        }
    }
}

// ---------------------------------------------------------------------------
extern "C" void kernel_launch(void* const* d_in, const int* in_sizes, int n_in,
                              void* d_out, int out_size)
{
    const float* x     = (const float*)d_in[0];
    const float* pos   = (const float*)d_in[1];
    const float* w_qkv = (const float*)d_in[2];
    const float* w_out = (const float*)d_in[3];
    const float* b_out = (const float*)d_in[4];
    float* out = (float*)d_out;

    static bool attr_set = false;
    if (!attr_set) {
        cudaFuncSetAttribute(flash_mma_kernel,
                             cudaFuncAttributeMaxDynamicSharedMemorySize,
                             SMEM_BYTES);
        cudaFuncSetAttribute(gemm_qkv_mma,
                             cudaFuncAttributeMaxDynamicSharedMemorySize,
                             GSMEM);
        cudaFuncSetAttribute(gemm_out_mma,
                             cudaFuncAttributeMaxDynamicSharedMemorySize,
                             GSMEM);
        attr_set = true;
    }

    conv_all_kernel<<<(N4ALL + 255) / 256, 256>>>(
        (const float4*)x, (const float4*)w_qkv, (const float4*)w_out);

    gemm_qkv_mma<<<dim3(QKVCOLS_ / 64, M_ / 128), 256, GSMEM>>>(pos);

    flash_mma_kernel<<<dim3(N_ / BR, B_ * H_), 256, SMEM_BYTES>>>();

    gemm_out_mma<<<dim3(C_ / 64, M_ / 128), 256, GSMEM>>>(b_out, out);
}

// round 14
// speedup vs baseline: 1.1930x; 1.1508x over previous
#include <cuda_runtime.h>
#include <cuda_bf16.h>
#include <cuda_fp16.h>
#include <cstdint>

// Problem constants
#define B_   2
#define N_   4096
#define C_   512
#define H_   8
#define D_   64
#define INNER_ (H_ * D_)          // 512
#define QKVCOLS_ (INNER_ * 3)     // 1536
#define M_ (B_ * N_)              // 8192
#define R_TOTAL (B_ * H_ * N_)    // 65536 rows of 64

// Scratch (device globals; no cudaMalloc allowed)
__device__ __half g_qh[R_TOTAL * D_];
__device__ __half g_kh[R_TOTAL * D_];
__device__ __half g_vh[R_TOTAL * D_];
__device__ __half g_xh[M_ * C_];
__device__ __half g_wq[C_ * QKVCOLS_];
__device__ __half g_wo[INNER_ * C_];
__device__ __half g_ohh[B_ * N_ * INNER_];

#define SCALE_LOG2E (0.125f * 1.4426950408889634f)

// ---------------------------------------------------------------------------
// common helpers
// ---------------------------------------------------------------------------
__device__ __forceinline__ uint32_t u32h2(__half2 v)
{
    return reinterpret_cast<uint32_t&>(v);
}
__device__ __forceinline__ float ex2(float x)
{
    float y;
    asm("ex2.approx.ftz.f32 %0, %1;" : "=f"(y) : "f"(x));
    return y;
}
__device__ __forceinline__ uint32_t hex2(__half2 v)
{
    uint32_t y;
    asm("ex2.approx.f16x2 %0, %1;" : "=r"(y) : "r"(u32h2(v)));
    return y;
}
__device__ __forceinline__ float2 h2f2(uint32_t h)
{
    return __half22float2(reinterpret_cast<__half2&>(h));
}
__device__ __forceinline__ uint32_t swz(uint32_t row, uint32_t colb)
{
    uint32_t b = (row << 7) + colb;     // 128B rows
    return b ^ ((b >> 3) & 0x70);
}
__device__ __forceinline__ uint32_t swzA(uint32_t row, uint32_t colb)
{
    uint32_t b = (row << 6) + colb;     // 64B rows
    return b ^ ((b >> 3) & 0x30);
}
__device__ __forceinline__ void cp16(uint32_t dst, const void* src)
{
    asm volatile("cp.async.cg.shared.global [%0], [%1], 16;"
                 :: "r"(dst), "l"(src));
}
__device__ __forceinline__ void cp_commit()
{
    asm volatile("cp.async.commit_group;");
}
__device__ __forceinline__ void cp_wait0()
{
    asm volatile("cp.async.wait_group 0;");
}
__device__ __forceinline__ void cp_wait1()
{
    asm volatile("cp.async.wait_group 1;");
}
__device__ __forceinline__ void ldsm4(uint32_t a[4], uint32_t addr)
{
    asm volatile("ldmatrix.sync.aligned.m8n8.x4.shared.b16 {%0,%1,%2,%3}, [%4];"
                 : "=r"(a[0]), "=r"(a[1]), "=r"(a[2]), "=r"(a[3]) : "r"(addr));
}
__device__ __forceinline__ void ldsm4t(uint32_t a[4], uint32_t addr)
{
    asm volatile("ldmatrix.sync.aligned.m8n8.x4.trans.shared.b16 {%0,%1,%2,%3}, [%4];"
                 : "=r"(a[0]), "=r"(a[1]), "=r"(a[2]), "=r"(a[3]) : "r"(addr));
}
__device__ __forceinline__ void mma16816h(float c[4], const uint32_t a[4],
                                          uint32_t b0, uint32_t b1)
{
    asm volatile(
        "mma.sync.aligned.m16n8k16.row.col.f32.f16.f16.f32 "
        "{%0,%1,%2,%3}, {%4,%5,%6,%7}, {%8,%9}, {%0,%1,%2,%3};"
        : "+f"(c[0]), "+f"(c[1]), "+f"(c[2]), "+f"(c[3])
        : "r"(a[0]), "r"(a[1]), "r"(a[2]), "r"(a[3]), "r"(b0), "r"(b1));
}

// ---------------------------------------------------------------------------
// K0: merged conversion — x, w_qkv, w_out -> fp16 single.
// ---------------------------------------------------------------------------
#define N4X  (M_ * C_ / 4)
#define N4WQ (C_ * QKVCOLS_ / 4)
#define N4WO (INNER_ * C_ / 4)
#define N4ALL (N4X + N4WQ + N4WO)

__global__ __launch_bounds__(256) void conv_all_kernel(
    const float4* __restrict__ x, const float4* __restrict__ wq,
    const float4* __restrict__ wo)
{
    int i = blockIdx.x * 256 + threadIdx.x;
    if (i < N4X) {
        float4 f = x[i];
        ((uint2*)g_xh)[i] = make_uint2(u32h2(__floats2half2_rn(f.x, f.y)),
                                       u32h2(__floats2half2_rn(f.z, f.w)));
    } else if (i < N4X + N4WQ) {
        int j = i - N4X;
        float4 f = wq[j];
        ((uint2*)g_wq)[j] = make_uint2(u32h2(__floats2half2_rn(f.x, f.y)),
                                       u32h2(__floats2half2_rn(f.z, f.w)));
    } else if (i < N4ALL) {
        int j = i - N4X - N4WQ;
        float4 f = wo[j];
        ((uint2*)g_wo)[j] = make_uint2(u32h2(__floats2half2_rn(f.x, f.y)),
                                       u32h2(__floats2half2_rn(f.z, f.w)));
    }
}

// ---------------------------------------------------------------------------
// Shared GEMM machinery. BM=128, BN=64, BK=32, 3-stage cp.async,
// fp16 SINGLE-term A and B. 8 warps, 8m x 1n (warp tile 16x64).
// ---------------------------------------------------------------------------
#define GSA   0
#define GSB   8192
#define GSTAGE 12288
#define GSMEM (3 * GSTAGE)   // 36864
#define GNKT (C_ / 32)       // 16

__device__ __forceinline__ void gemm_stage(
    uint32_t sb, uint32_t stg,
    const __half* __restrict__ aw, const __half* __restrict__ bw,
    int m0, int n0, int k0, int ldb, int tid)
{
    #pragma unroll
    for (int i = 0; i < 3; i++) {
        int c = tid + i * 256;               // 0..767
        if (c < 512) {
            int row = c >> 2, col16 = c & 3;
            cp16(sb + stg + GSA + swzA(row, col16 * 16),
                 aw + (size_t)(m0 + row) * C_ + k0 + col16 * 8);
        } else {
            int cc = c - 512;                // 0..255
            int row = cc >> 3, col16 = cc & 7;
            cp16(sb + stg + GSB + swz(row, col16 * 16),
                 bw + (size_t)(k0 + row) * ldb + n0 + col16 * 8);
        }
    }
}

__device__ __forceinline__ void gemm_compute(
    uint32_t sb, uint32_t stg, float c[8][4], int wid, int lane)
{
    const int rA = lane & 15;
    const int cadd = (lane & 16) ? 16 : 0;
    #pragma unroll
    for (int t = 0; t < 2; t++) {
        uint32_t AH[4], BW[4][4];
        ldsm4(AH, sb + stg + GSA + swzA(wid * 16 + rA, t * 32 + cadd));
        #pragma unroll
        for (int j2 = 0; j2 < 4; j2++) {
            uint32_t off = swz(t * 16 + rA, j2 * 32 + cadd);
            ldsm4t(BW[j2], sb + stg + GSB + off);
        }
        #pragma unroll
        for (int j2 = 0; j2 < 4; j2++) {
            mma16816h(c[2 * j2],     AH, BW[j2][0], BW[j2][1]);
            mma16816h(c[2 * j2 + 1], AH, BW[j2][2], BW[j2][3]);
        }
    }
}

// K1: QKV GEMM. grid (24, 64). Fused epilogue: RoPE + scale(q) + fp16 scatter.
__global__ __launch_bounds__(256) void gemm_qkv_mma(const float* __restrict__ pos)
{
    extern __shared__ char smemq[];
    const uint32_t sb = (uint32_t)__cvta_generic_to_shared(smemq);
    const int tid = threadIdx.x;
    const int wid = tid >> 5, lane = tid & 31;
    const int m0 = blockIdx.y * 128;
    const int n0 = blockIdx.x * 64;

    float c[8][4] = {};

    gemm_stage(sb, 0,      g_xh, g_wq, m0, n0, 0,  QKVCOLS_, tid);
    cp_commit();
    gemm_stage(sb, GSTAGE, g_xh, g_wq, m0, n0, 32, QKVCOLS_, tid);
    cp_commit();

    for (int kt = 0; kt < GNKT; kt++) {
        if (kt < GNKT - 1) cp_wait1(); else cp_wait0();
        __syncthreads();
        if (kt + 2 < GNKT) {
            gemm_stage(sb, ((kt + 2) % 3) * GSTAGE, g_xh, g_wq,
                       m0, n0, (kt + 2) * 32, QKVCOLS_, tid);
            cp_commit();
        }
        gemm_compute(sb, (kt % 3) * GSTAGE, c, wid, lane);
    }

    const int part = n0 >> 9;                          // 0=q, 1=k, 2=v
    const int h = (n0 & 511) >> 6;
    __half* dst = (part == 0) ? g_qh : (part == 1) ? g_kh : g_vh;

    #pragma unroll
    for (int r8 = 0; r8 < 2; r8++) {
        const int mrow = m0 + wid * 16 + r8 * 8 + (lane >> 2);
        const int b = mrow >> 12;
        const int n = mrow & (N_ - 1);
        const size_t base = ((size_t)(b * H_ + h) * N_ + n) * D_;
        #pragma unroll
        for (int nj = 0; nj < 8; nj++) {
            const int dd = nj * 8 + (lane & 3) * 2;
            float v0 = c[nj][2 * r8];
            float v1 = c[nj][2 * r8 + 1];
            float r0, r1;
            if (part < 2) {
                float s0, c0, s1, c1;
                __sincosf(pos[n * D_ + dd],     &s0, &c0);
                __sincosf(pos[n * D_ + dd + 1], &s1, &c1);
                const float q0 = c[nj ^ 4][2 * r8];
                const float q1 = c[nj ^ 4][2 * r8 + 1];
                const float sign = (nj < 4) ? -1.0f : 1.0f;
                r0 = v0 * c0 + sign * q0 * s0;
                r1 = v1 * c1 + sign * q1 * s1;
                if (part == 0) { r0 *= SCALE_LOG2E; r1 *= SCALE_LOG2E; }
            } else {
                r0 = v0; r1 = v1;
            }
            *(uint32_t*)&dst[base + dd] = u32h2(__floats2half2_rn(r0, r1));
        }
    }
}

// K4: output GEMM. grid (8, 64).
__global__ __launch_bounds__(256) void gemm_out_mma(
    const float* __restrict__ bias, float* __restrict__ out)
{
    extern __shared__ char smemo[];
    const uint32_t sb = (uint32_t)__cvta_generic_to_shared(smemo);
    const int tid = threadIdx.x;
    const int wid = tid >> 5, lane = tid & 31;
    const int m0 = blockIdx.y * 128;
    const int n0 = blockIdx.x * 64;

    float c[8][4] = {};

    gemm_stage(sb, 0,      g_ohh, g_wo, m0, n0, 0,  C_, tid);
    cp_commit();
    gemm_stage(sb, GSTAGE, g_ohh, g_wo, m0, n0, 32, C_, tid);
    cp_commit();

    for (int kt = 0; kt < GNKT; kt++) {
        if (kt < GNKT - 1) cp_wait1(); else cp_wait0();
        __syncthreads();
        if (kt + 2 < GNKT) {
            gemm_stage(sb, ((kt + 2) % 3) * GSTAGE, g_ohh, g_wo,
                       m0, n0, (kt + 2) * 32, C_, tid);
            cp_commit();
        }
        gemm_compute(sb, (kt % 3) * GSTAGE, c, wid, lane);
    }

    #pragma unroll
    for (int r8 = 0; r8 < 2; r8++) {
        const int mrow = m0 + wid * 16 + r8 * 8 + (lane >> 2);
        #pragma unroll
        for (int nj = 0; nj < 8; nj++) {
            const int col = n0 + nj * 8 + (lane & 3) * 2;
            *(float2*)&out[(size_t)mrow * C_ + col] =
                make_float2(c[nj][2 * r8] + bias[col],
                            c[nj][2 * r8 + 1] + bias[col + 1]);
        }
    }
}

// ---------------------------------------------------------------------------
// K3: flash attention, BR=256 (warp = 32 q-rows, 2 m16 groups), BC=64.
// ---------------------------------------------------------------------------
#define BR 256
#define BC 64
#define NT (N_ / BC)       // 64

#define SQ    0            // 32 KB
#define SKV   32768        // + stage*16384 ; K at +0, V at +8192
#define SMEM_BYTES 65536

__global__ __launch_bounds__(256, 1) void flash_mma_kernel()
{
    extern __shared__ char smraw[];
    const uint32_t sb = (uint32_t)__cvta_generic_to_shared(smraw);

    const int tid = threadIdx.x;
    const int wid = tid >> 5;
    const int lane = tid & 31;
    const int bh = blockIdx.y;
    const int b = bh >> 3, h = bh & 7;
    const int q0 = blockIdx.x * BR;

    // ---- stage Q (256 rows) ----
    {
        const size_t qbase = ((size_t)bh * N_ + q0) * D_;
        #pragma unroll
        for (int i = 0; i < 8; i++) {
            int c = tid + i * 256;            // 0..2047
            int row = c >> 3;
            int col16 = c & 7;
            cp16(sb + SQ + swz(row, col16 * 16),
                 g_qh + qbase + (size_t)row * D_ + col16 * 8);
        }
    }
    // ---- stage KV tile 0 ----
    {
        const size_t kvbase = (size_t)bh * N_ * D_;
        #pragma unroll
        for (int i = 0; i < 4; i++) {
            int c = tid + i * 256;            // 0..1023
            int arr = c >> 9;                 // 0=K, 1=V
            int cc = c & 511;
            int row = cc >> 3;
            int col16 = cc & 7;
            cp16(sb + SKV + (arr ? 8192 : 0) + swz(row, col16 * 16),
                 (arr ? g_vh : g_kh) + kvbase + (size_t)row * D_ + col16 * 8);
        }
    }
    cp_commit();
    cp_wait0();
    __syncthreads();

    // ---- Q fragments: 2 groups x 4 k-chunks ----
    const int m0 = wid * 32;
    uint32_t qh[2][4][4];
    {
        const int cadd = (lane & 16) ? 16 : 0;
        #pragma unroll
        for (int g = 0; g < 2; g++) {
            int r = m0 + g * 16 + (lane & 15);
            #pragma unroll
            for (int t = 0; t < 4; t++)
                ldsm4(qh[g][t], sb + SQ + swz(r, t * 32 + cadd));
        }
    }

    float o[2][8][4] = {};
    float mrow[2][2] = {{-1e30f, -1e30f}, {-1e30f, -1e30f}};
    float lrow[2][2] = {};

    const size_t kvstride = (size_t)bh * N_ * D_;

    for (int kt = 0; kt < NT; kt++) {
        const uint32_t buf = (kt & 1) ? 16384 : 0;
        const uint32_t nbuf = (kt & 1) ? 0 : 16384;

        if (kt + 1 < NT) {
            const size_t kvbase = kvstride + (size_t)(kt + 1) * BC * D_;
            #pragma unroll
            for (int i = 0; i < 4; i++) {
                int c = tid + i * 256;
                int arr = c >> 9;
                int cc = c & 511;
                int row = cc >> 3;
                int col16 = cc & 7;
                cp16(sb + SKV + nbuf + (arr ? 8192 : 0) + swz(row, col16 * 16),
                     (arr ? g_vh : g_kh) + kvbase + (size_t)row * D_ + col16 * 8);
            }
            cp_commit();
        }

        // ---- S = Q K^T ----
        float s[2][8][4] = {};
        {
            const int rbase = lane & 15;
            const int cadd = (lane & 16) ? 16 : 0;
            #pragma unroll
            for (int p = 0; p < 4; p++) {
                #pragma unroll
                for (int t = 0; t < 4; t++) {
                    uint32_t KH[4];
                    ldsm4(KH, sb + SKV + buf + swz(p * 16 + rbase, t * 32 + cadd));
                    #pragma unroll
                    for (int g = 0; g < 2; g++) {
                        mma16816h(s[g][2 * p],     qh[g][t], KH[0], KH[2]);
                        mma16816h(s[g][2 * p + 1], qh[g][t], KH[1], KH[3]);
                    }
                }
            }
        }

        // ---- online softmax per group ----
        float mn[2][2], al[2][2];
        #pragma unroll
        for (int g = 0; g < 2; g++) {
            float rmax0 = -1e30f, rmax1 = -1e30f;
            #pragma unroll
            for (int ni = 0; ni < 8; ni++) {
                rmax0 = fmaxf(rmax0, fmaxf(s[g][ni][0], s[g][ni][1]));
                rmax1 = fmaxf(rmax1, fmaxf(s[g][ni][2], s[g][ni][3]));
            }
            rmax0 = fmaxf(rmax0, __shfl_xor_sync(0xffffffffu, rmax0, 1));
            rmax0 = fmaxf(rmax0, __shfl_xor_sync(0xffffffffu, rmax0, 2));
            rmax1 = fmaxf(rmax1, __shfl_xor_sync(0xffffffffu, rmax1, 1));
            rmax1 = fmaxf(rmax1, __shfl_xor_sync(0xffffffffu, rmax1, 2));

            mn[g][0] = fmaxf(mrow[g][0], rmax0);
            mn[g][1] = fmaxf(mrow[g][1], rmax1);
            al[g][0] = ex2(mrow[g][0] - mn[g][0]);
            al[g][1] = ex2(mrow[g][1] - mn[g][1]);
            mrow[g][0] = mn[g][0]; mrow[g][1] = mn[g][1];

            #pragma unroll
            for (int ni = 0; ni < 8; ni++) {
                o[g][ni][0] *= al[g][0]; o[g][ni][1] *= al[g][0];
                o[g][ni][2] *= al[g][1]; o[g][ni][3] *= al[g][1];
            }
        }

        // ---- P=exp2(S-mn) fp16; O += P V; l += sum(P) ----
        float sum[2][2] = {};
        #pragma unroll
        for (int t = 0; t < 4; t++) {
            uint32_t ah[2][4];
            #pragma unroll
            for (int g = 0; g < 2; g++) {
                const float* p0 = s[g][2 * t];
                const float* p1 = s[g][2 * t + 1];
                ah[g][0] = hex2(__floats2half2_rn(p0[0] - mn[g][0],
                                                  p0[1] - mn[g][0]));
                ah[g][1] = hex2(__floats2half2_rn(p0[2] - mn[g][1],
                                                  p0[3] - mn[g][1]));
                ah[g][2] = hex2(__floats2half2_rn(p1[0] - mn[g][0],
                                                  p1[1] - mn[g][0]));
                ah[g][3] = hex2(__floats2half2_rn(p1[2] - mn[g][1],
                                                  p1[3] - mn[g][1]));
                float2 f0 = h2f2(ah[g][0]), f1 = h2f2(ah[g][1]);
                float2 f2 = h2f2(ah[g][2]), f3 = h2f2(ah[g][3]);
                sum[g][0] += (f0.x + f0.y) + (f2.x + f2.y);
                sum[g][1] += (f1.x + f1.y) + (f3.x + f3.y);
            }
            const int rr = t * 16 + (lane & 15);
            const int cadd = (lane & 16) ? 16 : 0;
            #pragma unroll
            for (int dp = 0; dp < 4; dp++) {
                uint32_t VH[4];
                ldsm4t(VH, sb + SKV + buf + 8192 + swz(rr, dp * 32 + cadd));
                #pragma unroll
                for (int g = 0; g < 2; g++) {
                    mma16816h(o[g][2 * dp],     ah[g], VH[0], VH[1]);
                    mma16816h(o[g][2 * dp + 1], ah[g], VH[2], VH[3]);
                }
            }
        }
        #pragma unroll
        for (int g = 0; g < 2; g++) {
            sum[g][0] += __shfl_xor_sync(0xffffffffu, sum[g][0], 1);
            sum[g][0] += __shfl_xor_sync(0xffffffffu, sum[g][0], 2);
            sum[g][1] += __shfl_xor_sync(0xffffffffu, sum[g][1], 1);
            sum[g][1] += __shfl_xor_sync(0xffffffffu, sum[g][1], 2);
            lrow[g][0] = lrow[g][0] * al[g][0] + sum[g][0];
            lrow[g][1] = lrow[g][1] * al[g][1] + sum[g][1];
        }

        cp_wait0();
        __syncthreads();
    }

    // ---- normalize + write O (fp16 single) to [B,N,H*d] ----
    #pragma unroll
    for (int g = 0; g < 2; g++) {
        const float inv0 = 1.0f / lrow[g][0];
        const float inv1 = 1.0f / lrow[g][1];
        const int r0 = q0 + m0 + g * 16 + (lane >> 2);
        const int cb = 2 * (lane & 3);
        const size_t base0 = ((size_t)(b * N_ + r0)) * INNER_ + h * D_;
        const size_t base1 = ((size_t)(b * N_ + r0 + 8)) * INNER_ + h * D_;
        #pragma unroll
        for (int ni = 0; ni < 8; ni++) {
            int dd = ni * 8 + cb;
            *(uint32_t*)&g_ohh[base0 + dd] =
                u32h2(__floats2half2_rn(o[g][ni][0] * inv0,
                                        o[g][ni][1] * inv0));
            *(uint32_t*)&g_ohh[base1 + dd] =
                u32h2(__floats2half2_rn(o[g][ni][2] * inv1,
                                        o[g][ni][3] * inv1));
        }
    }
}

// ---------------------------------------------------------------------------
extern "C" void kernel_launch(void* const* d_in, const int* in_sizes, int n_in,
                              void* d_out, int out_size)
{
    const float* x     = (const float*)d_in[0];
    const float* pos   = (const float*)d_in[1];
    const float* w_qkv = (const float*)d_in[2];
    const float* w_out = (const float*)d_in[3];
    const float* b_out = (const float*)d_in[4];
    float* out = (float*)d_out;

    static bool attr_set = false;
    if (!attr_set) {
        cudaFuncSetAttribute(flash_mma_kernel,
                             cudaFuncAttributeMaxDynamicSharedMemorySize,
                             SMEM_BYTES);
        cudaFuncSetAttribute(gemm_qkv_mma,
                             cudaFuncAttributeMaxDynamicSharedMemorySize,
                             GSMEM);
        cudaFuncSetAttribute(gemm_out_mma,
                             cudaFuncAttributeMaxDynamicSharedMemorySize,
                             GSMEM);
        attr_set = true;
    }

    conv_all_kernel<<<(N4ALL + 255) / 256, 256>>>(
        (const float4*)x, (const float4*)w_qkv, (const float4*)w_out);

    gemm_qkv_mma<<<dim3(QKVCOLS_ / 64, M_ / 128), 256, GSMEM>>>(pos);

    flash_mma_kernel<<<dim3(N_ / BR, B_ * H_), 256, SMEM_BYTES>>>();

    gemm_out_mma<<<dim3(C_ / 64, M_ / 128), 256, GSMEM>>>(b_out, out);
}